// round 6
// baseline (speedup 1.0000x reference)
#include <cuda_runtime.h>
#include <cstdint>
#include <cstddef>

#define BATCH   8
#define NPTS    8192
#define CDIM    6
#define NG      512
#define GS      32
#define FULLMASK 0xffffffffu

// output layout: neighborhood, center, idx (flattened tuple order, all f32)
#define NB_SZ  (BATCH * NG * GS * CDIM)   // 786432
#define C_OFF  (NB_SZ)
#define C_SZ   (BATCH * NG * 3)           // 12288
#define I_OFF  (C_OFF + C_SZ)             // 798720
#define I_SZ   (BATCH * NG * GS)          // 131072

// scratch (no allocations allowed -> __device__ globals)
__device__ float4 g_pts[BATCH * NPTS];    // (x, y, z, |p|^2)
__device__ float4 g_center[BATCH * NG];   // (cx, cy, cz, |c|^2)

// ---------------------------------------------------------------------------
// packed f32x2 helpers (Blackwell FFMA2 path; per-component RN rounding is
// identical to the scalar FMUL/FFMA chain, so selection stays bit-exact)
// ---------------------------------------------------------------------------
__device__ __forceinline__ unsigned long long pk2(float lo, float hi) {
    unsigned long long r;
    asm("mov.b64 %0, {%1, %2};" : "=l"(r)
        : "r"(__float_as_uint(lo)), "r"(__float_as_uint(hi)));
    return r;
}
__device__ __forceinline__ void upk2(unsigned long long v, float& lo, float& hi) {
    unsigned a, b;
    asm("mov.b64 {%0, %1}, %2;" : "=r"(a), "=r"(b) : "l"(v));
    lo = __uint_as_float(a); hi = __uint_as_float(b);
}
__device__ __forceinline__ unsigned long long add2(unsigned long long a, unsigned long long b) {
    unsigned long long r;
    asm("add.rn.f32x2 %0, %1, %2;" : "=l"(r) : "l"(a), "l"(b));
    return r;
}
__device__ __forceinline__ unsigned long long mul2(unsigned long long a, unsigned long long b) {
    unsigned long long r;
    asm("mul.rn.f32x2 %0, %1, %2;" : "=l"(r) : "l"(a), "l"(b));
    return r;
}
__device__ __forceinline__ unsigned long long fma2(unsigned long long a, unsigned long long b,
                                                   unsigned long long c) {
    unsigned long long r;
    asm("fma.rn.f32x2 %0, %1, %2, %3;" : "=l"(r) : "l"(a), "l"(b), "l"(c));
    return r;
}

// Sum of squares, one canonical rounding at every site: t=x*x; fma(y,y,t); fma(z,z,t)
__device__ __forceinline__ float sumsq3(float x, float y, float z) {
    float t = __fmul_rn(x, x);
    t = __fmaf_rn(y, y, t);
    t = __fmaf_rn(z, z, t);
    return t;
}

// ---------------------------------------------------------------------------
// FPS: one CTA of 512 threads per batch, 16 pts/thread register-resident.
// Per step: packed-f32x2 distance update, redux-based argmax (tie -> lowest
// index), ONE __syncthreads (partials double-buffered by step parity), every
// warp redundantly reduces the 16 warp partials. Unchanged from R5 (passing).
// ---------------------------------------------------------------------------
#define FT  512
__global__ void __launch_bounds__(FT, 1)
fps_kernel(const float* __restrict__ xyz, float* __restrict__ out, int out_size) {
    const int b   = blockIdx.x;
    const int tid = threadIdx.x;
    extern __shared__ float sh[];
    float* sx = sh;
    float* sy = sh + NPTS;
    float* sz = sh + 2 * NPTS;
    unsigned* sv = (unsigned*)(sh + 3 * NPTS);   // [2][16] partial values
    unsigned* sidx = sv + 32;                    // [2][16] partial indices

    const float* base = xyz + (size_t)b * NPTS * CDIM;
    unsigned long long pxx[8], pyy[8], pzz[8];
    float dist[16];
    float prx = 0.f, pry = 0.f, prz = 0.f;
#pragma unroll
    for (int j = 0; j < 16; j++) {
        int i = j * FT + tid;
        float x = base[i * CDIM + 0];
        float y = base[i * CDIM + 1];
        float z = base[i * CDIM + 2];
        sx[i] = x; sy[i] = y; sz[i] = z;
        g_pts[b * NPTS + i] = make_float4(x, y, z, sumsq3(x, y, z));
        dist[j] = __int_as_float(0x7f800000);    // +inf
        if ((j & 1) == 0) { prx = x; pry = y; prz = z; }
        else {
            pxx[j >> 1] = pk2(prx, x);
            pyy[j >> 1] = pk2(pry, y);
            pzz[j >> 1] = pk2(prz, z);
        }
    }
    __syncthreads();

    float qx = sx[0], qy = sy[0], qz = sz[0];    // first FPS point is index 0
    if (tid == 0) {
        g_center[b * NG] = make_float4(qx, qy, qz, sumsq3(qx, qy, qz));
        if (out_size >= C_OFF + C_SZ) {
            out[C_OFF + (size_t)(b * NG) * 3 + 0] = qx;
            out[C_OFF + (size_t)(b * NG) * 3 + 1] = qy;
            out[C_OFF + (size_t)(b * NG) * 3 + 2] = qz;
        }
    }

    const int lane = tid & 31, wid = tid >> 5;
    for (int k = 1; k < NG; k++) {
        const unsigned long long nqx2 = pk2(-qx, -qx);
        const unsigned long long nqy2 = pk2(-qy, -qy);
        const unsigned long long nqz2 = pk2(-qz, -qz);
        float v = -1.0f; unsigned vi = 0;
#pragma unroll
        for (int j = 0; j < 8; j++) {
            // per component: dx = px + (-qx)  (== px - qx exactly)
            unsigned long long dx2 = add2(pxx[j], nqx2);
            unsigned long long dy2 = add2(pyy[j], nqy2);
            unsigned long long dz2 = add2(pzz[j], nqz2);
            unsigned long long t  = mul2(dx2, dx2);
            t = fma2(dy2, dy2, t);
            t = fma2(dz2, dz2, t);
            float dlo, dhi; upk2(t, dlo, dhi);
            float nd = fminf(dist[2 * j], dlo);
            dist[2 * j] = nd;
            if (nd > v) { v = nd; vi = (unsigned)((2 * j) * FT + tid); }
            nd = fminf(dist[2 * j + 1], dhi);
            dist[2 * j + 1] = nd;
            if (nd > v) { v = nd; vi = (unsigned)((2 * j + 1) * FT + tid); }
        }
        // level-1: warp argmax, tie -> lowest index (v >= 0 so bits are monotone)
        unsigned vb = __float_as_uint(v);
        unsigned M  = __reduce_max_sync(FULLMASK, vb);
        unsigned cand = (vb == M) ? vi : 0xffffffffu;
        unsigned mi = __reduce_min_sync(FULLMASK, cand);
        const int slot = (k & 1) << 4;
        if (lane == 0) { sv[slot + wid] = M; sidx[slot + wid] = mi; }
        __syncthreads();
        // level-2: every warp redundantly reduces the 16 partials
        int l = slot + (lane & 15);
        unsigned pv = sv[l], pi = sidx[l];
        unsigned M2 = __reduce_max_sync(FULLMASK, pv);
        unsigned cand2 = (pv == M2) ? pi : 0xffffffffu;
        unsigned far = __reduce_min_sync(FULLMASK, cand2);
        qx = sx[far]; qy = sy[far]; qz = sz[far];
        if (tid == 0) {
            g_center[b * NG + k] = make_float4(qx, qy, qz, sumsq3(qx, qy, qz));
            if (out_size >= C_OFF + C_SZ) {
                out[C_OFF + (size_t)(b * NG + k) * 3 + 0] = qx;
                out[C_OFF + (size_t)(b * NG + k) * 3 + 1] = qy;
                out[C_OFF + (size_t)(b * NG + k) * 3 + 2] = qz;
            }
        }
    }
}

// ---------------------------------------------------------------------------
// kNN top-32 + gather. NEW: 4 warps per group (block=128 = 1 group); each warp
// scans a 2048-candidate slice into a local sorted top-32, then a 2-level
// bitonic merge combines slices. Selection under total order (d2, idx) is
// split/merge-invariant => bit-identical result to the single-warp version.
// Distance chain (bit-exact to passing versions):
//   dot: FMUL; FFMA; FFMA   d2: fsub(fadd(cc, pp), fmul(2, dot))
// ---------------------------------------------------------------------------
__device__ __forceinline__ float ref_dist(float4 c, float x, float y, float z, float p2) {
    float dot = __fmul_rn(c.x, x);
    dot = __fmaf_rn(c.y, y, dot);
    dot = __fmaf_rn(c.z, z, dot);
    return __fsub_rn(__fadd_rn(c.w, p2), __fmul_rn(2.0f, dot));
}

__device__ __forceinline__ bool key_less(float ad, int ai, float bd, int bi) {
    return (ad < bd) || (ad == bd && ai < bi);   // JAX top_k tie rule: lower index wins
}

// sort an ascending run from a bitonic sequence (5-step cleanup)
__device__ __forceinline__ void bitonic_cleanup(float& Sd, int& Si, int lane) {
#pragma unroll
    for (int j = 16; j > 0; j >>= 1) {
        float od = __shfl_xor_sync(FULLMASK, Sd, j);
        int   oi = __shfl_xor_sync(FULLMASK, Si, j);
        bool lower = key_less(od, oi, Sd, Si);
        bool takeSmaller = ((lane & j) == 0);
        if (lower == takeSmaller) { Sd = od; Si = oi; }
    }
}

#define KNN_SLICE 2048                     // NPTS / 4 warps

__global__ void __launch_bounds__(128, 12)
knn_kernel(const float* __restrict__ xyz, float* __restrict__ out, int out_size) {
    const int lane = threadIdx.x & 31;
    const int wg   = threadIdx.x >> 5;     // warp-in-group, 0..3
    const int grp  = blockIdx.x;           // global group id, 0..4095
    const int b    = grp >> 9;             // / NG
    const float4 c = g_center[grp];
    const float4* pts = g_pts + b * NPTS;

    __shared__ float sD[3 * 32];           // lists 1, 3 and merged 2
    __shared__ int   sI[3 * 32];

    const int sbase = wg * KNN_SLICE;
    float Sd; int Si;
    {
        float4 p = pts[sbase + lane];
        Sd = ref_dist(c, p.x, p.y, p.z, p.w);
        Si = sbase + lane;
    }
    // bitonic sort first 32 slice candidates ascending across lanes
#pragma unroll
    for (int k = 2; k <= 32; k <<= 1) {
        const bool dd = (lane & k) != 0;
#pragma unroll
        for (int j = k >> 1; j > 0; j >>= 1) {
            float od = __shfl_xor_sync(FULLMASK, Sd, j);
            int   oi = __shfl_xor_sync(FULLMASK, Si, j);
            bool lower = key_less(od, oi, Sd, Si);
            bool takeSmaller = (((lane & j) == 0) != dd);
            if (lower == takeSmaller) { Sd = od; Si = oi; }
        }
    }
    float Td = __shfl_sync(FULLMASK, Sd, 31);
    int   Ti = __shfl_sync(FULLMASK, Si, 31);

    float4 p = pts[sbase + 32 + lane];
    for (int basei = sbase + 32; basei < sbase + KNN_SLICE; basei += 32) {
        float4 pn = p;
        if (basei + 32 < sbase + KNN_SLICE) pn = pts[basei + 32 + lane]; // pipeline
        const int i = basei + lane;
        float d = ref_dist(c, p.x, p.y, p.z, p.w);
        unsigned m = __ballot_sync(FULLMASK, key_less(d, i, Td, Ti));
        if (m) {
            do {
                int src = __ffs(m) - 1; m &= m - 1;
                float cd = __shfl_sync(FULLMASK, d, src);
                int   ci = basei + src;
                // stale-qualifying candidate worse than all 32 -> pos=32 -> no-op
                int pos = __popc(__ballot_sync(FULLMASK, key_less(Sd, Si, cd, ci)));
                float ud = __shfl_up_sync(FULLMASK, Sd, 1);
                int   ui = __shfl_up_sync(FULLMASK, Si, 1);
                if (lane == pos)      { Sd = cd; Si = ci; }
                else if (lane > pos)  { Sd = ud; Si = ui; }
            } while (m);
            Td = __shfl_sync(FULLMASK, Sd, 31);
            Ti = __shfl_sync(FULLMASK, Si, 31);
        }
        p = pn;
    }

    // publish odd warps' lists
    if (wg == 1) { sD[lane] = Sd;      sI[lane] = Si; }
    if (wg == 3) { sD[32 + lane] = Sd; sI[32 + lane] = Si; }
    __syncthreads();

    // round 1: warp0 merges list1, warp2 merges list3 (key-min vs reversed + cleanup)
    if (wg == 0 || wg == 2) {
        int off = (wg == 0) ? 0 : 32;
        float od = sD[off + 31 - lane];
        int   oi = sI[off + 31 - lane];
        if (key_less(od, oi, Sd, Si)) { Sd = od; Si = oi; }
        bitonic_cleanup(Sd, Si, lane);
    }
    if (wg == 2) { sD[64 + lane] = Sd; sI[64 + lane] = Si; }
    __syncthreads();

    // round 2: warp0 merges warp2's result -> final top-32, then gather+write
    if (wg == 0) {
        float od = sD[64 + 31 - lane];
        int   oi = sI[64 + 31 - lane];
        if (key_less(od, oi, Sd, Si)) { Sd = od; Si = oi; }
        bitonic_cleanup(Sd, Si, lane);

        const int n = Si;
        float4 pw = pts[n];                              // exact copies of xyz[:3]
        const float* pb = xyz + ((size_t)b * NPTS + n) * CDIM;
        float e0 = pb[3], e1 = pb[4], e2 = pb[5];
        float2 w0 = make_float2(pw.x - c.x, pw.y - c.y);
        float2 w1 = make_float2(pw.z - c.z, e0);
        float2 w2 = make_float2(e1, e2);
        float2* ob = (float2*)out + ((size_t)grp * GS + lane) * 3;
        ob[0] = w0; ob[1] = w1; ob[2] = w2;
        if (out_size >= I_OFF + I_SZ)
            out[I_OFF + (size_t)grp * GS + lane] = (float)n;
    }
}

extern "C" void kernel_launch(void* const* d_in, const int* in_sizes, int n_in,
                              void* d_out, int out_size) {
    const float* xyz = (const float*)d_in[0];
    float* out = (float*)d_out;
    (void)in_sizes; (void)n_in;

    const size_t smem = (size_t)(3 * NPTS) * sizeof(float) + 64 * sizeof(unsigned);
    cudaFuncSetAttribute(fps_kernel, cudaFuncAttributeMaxDynamicSharedMemorySize, (int)smem);

    fps_kernel<<<BATCH, FT, smem>>>(xyz, out, out_size);
    knn_kernel<<<BATCH * NG, 128>>>(xyz, out, out_size);
}